// round 1
// baseline (speedup 1.0000x reference)
#include <cuda_runtime.h>
#include <cmath>

#define BB 8
#define CC 256
#define HH 80
#define WW 80
#define HW (HH*WW)           // 6400
#define NPIX (BB*HW)         // 51200
#define PI_F 3.14159265358979323846f

// -------------------- scratch (static device globals; no cudaMalloc) -----
__device__ float g_h2[(size_t)BB*CC*HW];       // 52.4 MB
__device__ float g_buf1[(size_t)BB*2*CC*HW];   // 104.8 MB (up to 512 ch)
__device__ float g_buf2[(size_t)BB*2*CC*HW];   // 104.8 MB

__device__ __forceinline__ float gelu_exact(float v) {
    return 0.5f * v * (1.0f + erff(v * 0.70710678118654752f));
}

// ==========================================================================
// Kernel 1: fused BatchNorm + SpectralGating (closed-form Hilbert along W)
//   h2 = (a*s)*x + (b*s)*(x circ-conv t) + a*(beta - mean*s)
//   t[n] = -(2/W) cot(pi n / W) for odd n, else 0.
// block = 4 rows x 80 threads
// ==========================================================================
__global__ __launch_bounds__(320)
void spectral_kernel(const float* __restrict__ x,
                     const float* __restrict__ gamma,
                     const float* __restrict__ beta,
                     const float* __restrict__ mean,
                     const float* __restrict__ var,
                     const float* __restrict__ ar,
                     const float* __restrict__ ai,
                     float* __restrict__ out)
{
    __shared__ float taps[WW];
    __shared__ float xs[4][WW];

    const int tt = threadIdx.x;
    const int tn = tt % WW;
    const int tr = tt / WW;

    if (tt < WW) {
        float t = 0.0f;
        if (tt & 1) {
            float ang = PI_F * (float)tt / (float)WW;
            t = -(2.0f / (float)WW) * (cosf(ang) / sinf(ang));
        }
        taps[tt] = t;
    }

    const int row = blockIdx.x * 4 + tr;       // 0 .. B*C*H-1
    const int c = (row / HH) % CC;
    const size_t base = (size_t)row * WW;

    const float xv = x[base + tn];
    xs[tr][tn] = xv;
    __syncthreads();

    float u = 0.0f;
    #pragma unroll
    for (int j = 1; j < WW; j += 2) {
        int idx = tn - j;
        if (idx < 0) idx += WW;
        u += taps[j] * xs[tr][idx];
    }

    const float s   = gamma[c] * rsqrtf(var[c] + 1e-5f);
    const float tc  = beta[c] - mean[c] * s;
    const float A   = ar[c] * s;
    const float Bc  = ai[c] * s;
    const float Cc  = ar[c] * tc;

    out[base + tn] = A * xv + Bc * u + Cc;
}

// ==========================================================================
// Kernel 2: conv1x1 as GEMM.  out[b,o,p] = sum_c W[o,c]*in[b,c,p] + bias[o]
// Tiles: BM=128 (out ch), BN=128 (pixels), BK=16. 256 threads, 8x8 microtile.
// ACT: 0=none, 1=gelu.  RES: fuse residual add.
// ==========================================================================
template<int CIN, int COUT, int ACT, bool RES>
__global__ __launch_bounds__(256)
void conv1x1_kernel(const float* __restrict__ in,
                    const float* __restrict__ wgt,
                    const float* __restrict__ bias,
                    const float* __restrict__ res,
                    float* __restrict__ out)
{
    constexpr int BM = 128, BN = 128, BK = 16;
    __shared__ float As[BK][BM];
    __shared__ float Bs[BK][BN];

    const int bn = blockIdx.x * BN;          // pixel offset within batch
    const int bm = blockIdx.y * BM;          // out-channel offset
    const int bz = blockIdx.z;               // batch

    const float* inb  = in  + (size_t)bz * CIN  * HW;
    float*       outb = out + (size_t)bz * COUT * HW;
    const float* resb = RES ? (res + (size_t)bz * COUT * HW) : nullptr;

    const int tid = threadIdx.x;
    const int tx = tid % 16;                 // pixel group
    const int ty = tid / 16;                 // channel group

    float acc[8][8];
    #pragma unroll
    for (int i = 0; i < 8; i++)
        #pragma unroll
        for (int j = 0; j < 8; j++) acc[i][j] = 0.0f;

    // load mappings
    const int am = tid / 2;                  // 0..127 (row of W)
    const int akq = (tid % 2) * 8;           // 0 or 8 (k offset)
    const int bk = tid / 16;                 // 0..15 (k row of B tile)
    const int bc4 = (tid % 16) * 4;          // 0..60 (col quad)

    for (int k0 = 0; k0 < CIN; k0 += BK) {
        // As[kk][m] = wgt[(bm+m)*CIN + k0+kk]   (transpose on store)
        {
            const float4 w0 = *(const float4*)&wgt[(size_t)(bm + am) * CIN + k0 + akq];
            const float4 w1 = *(const float4*)&wgt[(size_t)(bm + am) * CIN + k0 + akq + 4];
            As[akq + 0][am] = w0.x; As[akq + 1][am] = w0.y;
            As[akq + 2][am] = w0.z; As[akq + 3][am] = w0.w;
            As[akq + 4][am] = w1.x; As[akq + 5][am] = w1.y;
            As[akq + 6][am] = w1.z; As[akq + 7][am] = w1.w;
        }
        // Bs[kk][n] = inb[(k0+kk)*HW + bn + n]
        {
            const float4 b0 = *(const float4*)&inb[(size_t)(k0 + bk) * HW + bn + bc4];
            const float4 b1 = *(const float4*)&inb[(size_t)(k0 + bk) * HW + bn + bc4 + 64];
            *(float4*)&Bs[bk][bc4]      = b0;
            *(float4*)&Bs[bk][bc4 + 64] = b1;
        }
        __syncthreads();

        #pragma unroll
        for (int kk = 0; kk < BK; kk++) {
            float a[8], b[8];
            const float4 a0 = *(const float4*)&As[kk][ty * 8];
            const float4 a1 = *(const float4*)&As[kk][ty * 8 + 4];
            const float4 b0 = *(const float4*)&Bs[kk][tx * 8];
            const float4 b1 = *(const float4*)&Bs[kk][tx * 8 + 4];
            a[0]=a0.x; a[1]=a0.y; a[2]=a0.z; a[3]=a0.w;
            a[4]=a1.x; a[5]=a1.y; a[6]=a1.z; a[7]=a1.w;
            b[0]=b0.x; b[1]=b0.y; b[2]=b0.z; b[3]=b0.w;
            b[4]=b1.x; b[5]=b1.y; b[6]=b1.z; b[7]=b1.w;
            #pragma unroll
            for (int i = 0; i < 8; i++)
                #pragma unroll
                for (int j = 0; j < 8; j++)
                    acc[i][j] = fmaf(a[i], b[j], acc[i][j]);
        }
        __syncthreads();
    }

    // epilogue
    #pragma unroll
    for (int i = 0; i < 8; i++) {
        const int m = bm + ty * 8 + i;
        const float bv = bias[m];
        float* orow = &outb[(size_t)m * HW + bn + tx * 8];
        #pragma unroll
        for (int j4 = 0; j4 < 2; j4++) {
            float4 v;
            v.x = acc[i][j4 * 4 + 0] + bv;
            v.y = acc[i][j4 * 4 + 1] + bv;
            v.z = acc[i][j4 * 4 + 2] + bv;
            v.w = acc[i][j4 * 4 + 3] + bv;
            if (ACT == 1) {
                v.x = gelu_exact(v.x); v.y = gelu_exact(v.y);
                v.z = gelu_exact(v.z); v.w = gelu_exact(v.w);
            }
            if (RES) {
                const float4 r = *(const float4*)&resb[(size_t)m * HW + bn + tx * 8 + j4 * 4];
                v.x += r.x; v.y += r.y; v.z += r.z; v.w += r.w;
            }
            *(float4*)&orow[j4 * 4] = v;
        }
    }
}

// ==========================================================================
// Kernel 3: depthwise 3x3 (SAME, zero pad) + bias + exact GELU
// ==========================================================================
__global__ __launch_bounds__(256)
void dwgelu_kernel(const float* __restrict__ in,
                   const float* __restrict__ w,
                   const float* __restrict__ b,
                   float* __restrict__ out)
{
    const int idx = blockIdx.x * 256 + threadIdx.x;   // over B*C*H*W
    const int wp = idx % WW;
    const int h  = (idx / WW) % HH;
    const int bc = idx / HW;
    const int c  = bc % CC;

    const float* p = in + (size_t)bc * HW;
    const float* wc = w + c * 9;

    float s = b[c];
    #pragma unroll
    for (int ky = 0; ky < 3; ky++) {
        const int hy = h + ky - 1;
        if (hy < 0 || hy >= HH) continue;
        #pragma unroll
        for (int kx = 0; kx < 3; kx++) {
            const int wx = wp + kx - 1;
            if (wx < 0 || wx >= WW) continue;
            s = fmaf(wc[ky * 3 + kx], p[hy * WW + wx], s);
        }
    }
    out[idx] = gelu_exact(s);
}

// ==========================================================================
// launch
// ==========================================================================
extern "C" void kernel_launch(void* const* d_in, const int* in_sizes, int n_in,
                              void* d_out, int out_size)
{
    const float* x        = (const float*)d_in[0];
    const float* bn_gamma = (const float*)d_in[1];
    const float* bn_beta  = (const float*)d_in[2];
    const float* bn_mean  = (const float*)d_in[3];
    const float* bn_var   = (const float*)d_in[4];
    const float* a_real   = (const float*)d_in[5];
    const float* a_imag   = (const float*)d_in[6];
    const float* pi_w     = (const float*)d_in[7];
    const float* pi_b     = (const float*)d_in[8];
    const float* dw_w     = (const float*)d_in[9];
    const float* dw_b     = (const float*)d_in[10];
    const float* fpw_w    = (const float*)d_in[11];
    const float* fpw_b    = (const float*)d_in[12];
    const float* ffn1_w   = (const float*)d_in[13];
    const float* ffn1_b   = (const float*)d_in[14];
    const float* ffn2_w   = (const float*)d_in[15];
    const float* ffn2_b   = (const float*)d_in[16];
    const float* po_w     = (const float*)d_in[17];
    const float* po_b     = (const float*)d_in[18];
    const float* post_w   = (const float*)d_in[19];
    const float* post_b   = (const float*)d_in[20];
    float* out = (float*)d_out;

    float* h2   = nullptr;
    float* buf1 = nullptr;
    float* buf2 = nullptr;
    cudaGetSymbolAddress((void**)&h2,   g_h2);
    cudaGetSymbolAddress((void**)&buf1, g_buf1);
    cudaGetSymbolAddress((void**)&buf2, g_buf2);

    // 1) BN + spectral gating (closed form)
    spectral_kernel<<<(BB * CC * HH) / 4, 320>>>(
        x, bn_gamma, bn_beta, bn_mean, bn_var, a_real, a_imag, h2);

    dim3 g256(HW / 128, CC / 128, BB);        // (50, 2, 8)
    dim3 g512(HW / 128, (2 * CC) / 128, BB);  // (50, 4, 8)

    // 2) proj_in
    conv1x1_kernel<256, 256, 0, false><<<g256, 256>>>(h2, pi_w, pi_b, nullptr, buf1);
    // 3) dw3x3 + gelu
    dwgelu_kernel<<<(BB * CC * HW) / 256, 256>>>(buf1, dw_w, dw_b, buf2);
    // 4) fpw
    conv1x1_kernel<256, 256, 0, false><<<g256, 256>>>(buf2, fpw_w, fpw_b, nullptr, buf1);
    // 5) ffn1 + gelu (256 -> 512)
    conv1x1_kernel<256, 512, 1, false><<<g512, 256>>>(buf1, ffn1_w, ffn1_b, nullptr, buf2);
    // 6) ffn2 (512 -> 256)
    conv1x1_kernel<512, 256, 0, false><<<g256, 256>>>(buf2, ffn2_w, ffn2_b, nullptr, buf1);
    // 7) proj_out + res2 (h2)
    conv1x1_kernel<256, 256, 0, true><<<g256, 256>>>(buf1, po_w, po_b, h2, buf2);
    // 8) post conv + outer residual (x)
    conv1x1_kernel<256, 256, 0, true><<<g256, 256>>>(buf2, post_w, post_b, x, out);
}